// round 2
// baseline (speedup 1.0000x reference)
#include <cuda_runtime.h>
#include <math.h>

#define BATCH   128
#define SEQ     512
#define INPUT   512
#define HIDDEN  1024
#define OUTPUT  256
#define NBLK    128

// Scratch (device globals: no allocation allowed)
__device__ float g_xin[(size_t)SEQ * BATCH * HIDDEN];   // [s][b][h] time-major for scan reads
__device__ float g_h[2][BATCH * HIDDEN];                // ping-pong hidden state
__device__ unsigned g_bar_cnt;
__device__ unsigned g_bar_gen;

// ---------------------------------------------------------------------------
// Device-wide barrier (all NBLK blocks resident; NBLK <= 148 SMs guarantees it)
// ---------------------------------------------------------------------------
__device__ __forceinline__ void grid_sync(unsigned target)
{
    __threadfence();           // make this thread's global writes visible
    __syncthreads();
    if (threadIdx.x == 0) {
        unsigned arrived = atomicAdd(&g_bar_cnt, 1u);
        if (arrived == NBLK - 1) {
            atomicExch(&g_bar_cnt, 0u);
            __threadfence();
            atomicAdd(&g_bar_gen, 1u);
        } else {
            while (*(volatile unsigned*)&g_bar_gen != target) { }
            __threadfence();
        }
    }
    __syncthreads();
}

// ---------------------------------------------------------------------------
// Phase 1: xin[s][b][n] = x[b][s][:] @ W_in[:, n] + b_in[n]
// Tiled fp32 GEMM: BM=64, BN=64, BK=16, 256 threads, 4x4 per thread.
// ---------------------------------------------------------------------------
__global__ __launch_bounds__(256) void gemm_xin_kernel(
    const float* __restrict__ x,
    const float* __restrict__ Win,
    const float* __restrict__ bin)
{
    __shared__ float As[16][64];   // [k][m]
    __shared__ float Bs[16][64];   // [k][n]

    const int tid = threadIdx.x;
    const int m0 = blockIdx.y * 64;
    const int n0 = blockIdx.x * 64;
    const int ty = tid >> 4;       // 0..15
    const int tx = tid & 15;       // 0..15

    float acc[4][4];
#pragma unroll
    for (int i = 0; i < 4; ++i)
#pragma unroll
        for (int j = 0; j < 4; ++j) acc[i][j] = 0.0f;

    const int arow = tid >> 2;     // 0..63
    const int akq  = tid & 3;      // 0..3  (k float4)
    const int brow = tid >> 4;     // 0..15 (k)
    const int bnq  = tid & 15;     // 0..15 (n float4)

    for (int k0 = 0; k0 < INPUT; k0 += 16) {
        float4 av = *(const float4*)(x   + (size_t)(m0 + arow) * INPUT  + k0 + akq * 4);
        float4 bv = *(const float4*)(Win + (size_t)(k0 + brow) * HIDDEN + n0 + bnq * 4);
        __syncthreads();
        As[akq * 4 + 0][arow] = av.x;
        As[akq * 4 + 1][arow] = av.y;
        As[akq * 4 + 2][arow] = av.z;
        As[akq * 4 + 3][arow] = av.w;
        *(float4*)&Bs[brow][bnq * 4] = bv;
        __syncthreads();
#pragma unroll
        for (int kk = 0; kk < 16; ++kk) {
            float4 a4 = *(const float4*)&As[kk][ty * 4];
            float4 b4 = *(const float4*)&Bs[kk][tx * 4];
            float a[4] = {a4.x, a4.y, a4.z, a4.w};
            float b[4] = {b4.x, b4.y, b4.z, b4.w};
#pragma unroll
            for (int i = 0; i < 4; ++i)
#pragma unroll
                for (int j = 0; j < 4; ++j)
                    acc[i][j] += a[i] * b[j];
        }
    }

    float4 bi = *(const float4*)(bin + n0 + tx * 4);
#pragma unroll
    for (int i = 0; i < 4; ++i) {
        int m = m0 + ty * 4 + i;
        int b = m >> 9;          // batch
        int s = m & 511;         // seq
        float4 r;
        r.x = acc[i][0] + bi.x;
        r.y = acc[i][1] + bi.y;
        r.z = acc[i][2] + bi.z;
        r.w = acc[i][3] + bi.w;
        *(float4*)(g_xin + ((size_t)s * BATCH + b) * HIDDEN + n0 + tx * 4) = r;
    }
}

// ---------------------------------------------------------------------------
// Phase 2+3: persistent scan kernel. 128 blocks = 8 batch-tiles x 16 j-tiles.
// Each step: z = xin_t + h_old @ W_h + b_h ; dx = tanh(z) ;
//            h_new = h_old + (dx - h_old) / tau ; grid barrier ; swap.
// Then out = h_final @ W_out + b_out (blocks 0..63).
// ---------------------------------------------------------------------------
#define SCAN_SMEM_FLOATS (16 * 1024 + 2 * 16 * 64 + 64 + 64)
#define SCAN_SMEM_BYTES  (SCAN_SMEM_FLOATS * 4)

__global__ __launch_bounds__(256, 1) void scan_kernel(
    const float* __restrict__ Wh,
    const float* __restrict__ bh,
    const float* __restrict__ tau,
    const float* __restrict__ Wout,
    const float* __restrict__ bout,
    float* __restrict__ out)
{
    extern __shared__ float smem[];
    float* h_s    = smem;              // [16][1024]  64 KB
    float* ws     = smem + 16 * 1024;  // [2][16][64]  8 KB (double-buffered W chunk)
    float* bh_s   = ws + 2048;         // [64]
    float* itau_s = bh_s + 64;         // [64]

    const int tid = threadIdx.x;
    const int bt  = blockIdx.x >> 4;   // 0..7  batch tile
    const int jt  = blockIdx.x & 15;   // 0..15 hidden tile
    const int b0  = bt * 16;
    const int j0  = jt * 64;
    const int ty  = tid >> 4;          // batch row 0..15
    const int tx  = tid & 15;          // j quad  0..15

    __shared__ unsigned sh_gen0;
    if (tid == 0) sh_gen0 = *(volatile unsigned*)&g_bar_gen;
    if (tid < 64) {
        bh_s[tid]   = bh[j0 + tid];
        itau_s[tid] = 1.0f / tau[j0 + tid];
    }
    // zero h0 (this block's [16 x 64] slice)
    {
        float4 z = make_float4(0.f, 0.f, 0.f, 0.f);
        *(float4*)(&g_h[0][(size_t)(b0 + ty) * HIDDEN + j0 + tx * 4]) = z;
    }
    __syncthreads();

    unsigned nbar = 0;
    grid_sync(sh_gen0 + (++nbar));

    const int wr = tid >> 4;   // W chunk row 0..15
    const int wc = tid & 15;   // W chunk col quad

    int cur = 0;
    for (int t = 0; t < SEQ; ++t) {
        const float* hsrc = g_h[cur];
        // Stage h_old [16 x 1024] into smem (L2-coherent loads; L1 may be stale)
        for (int q = tid; q < 16 * 256; q += 256) {
            int r = q >> 8;      // 0..15
            int c = q & 255;     // float4 index
            float4 v = __ldcg((const float4*)(hsrc + (size_t)(b0 + r) * HIDDEN) + c);
            *(float4*)&h_s[r * HIDDEN + c * 4] = v;
        }

        // acc = xin_t + b_h
        float4 acc = *(const float4*)(g_xin + ((size_t)t * BATCH + (b0 + ty)) * HIDDEN + j0 + tx * 4);
        acc.x += bh_s[tx * 4 + 0];
        acc.y += bh_s[tx * 4 + 1];
        acc.z += bh_s[tx * 4 + 2];
        acc.w += bh_s[tx * 4 + 3];

        // Preload W chunk 0
        float4 wv = *(const float4*)(Wh + (size_t)wr * HIDDEN + j0 + wc * 4);
        __syncthreads();                 // h_s fully staged, ws free
        *(float4*)&ws[0 * 1024 + wr * 64 + wc * 4] = wv;
        __syncthreads();

        for (int c = 0; c < 64; ++c) {
            if (c + 1 < 64)
                wv = *(const float4*)(Wh + (size_t)(16 * (c + 1) + wr) * HIDDEN + j0 + wc * 4);

            const float* hp = &h_s[ty * HIDDEN + c * 16];
            const float* wb = &ws[(c & 1) * 1024];
#pragma unroll
            for (int g = 0; g < 4; ++g) {
                float4 hg = *(const float4*)(hp + g * 4);
                float hx[4] = {hg.x, hg.y, hg.z, hg.w};
#pragma unroll
                for (int kk = 0; kk < 4; ++kk) {
                    float4 w = *(const float4*)&wb[(g * 4 + kk) * 64 + tx * 4];
                    float hv = hx[kk];
                    acc.x += hv * w.x;
                    acc.y += hv * w.y;
                    acc.z += hv * w.z;
                    acc.w += hv * w.w;
                }
            }
            if (c + 1 < 64)
                *(float4*)&ws[((c + 1) & 1) * 1024 + wr * 64 + wc * 4] = wv;
            __syncthreads();
        }

        // h update
        float4 hold = *(const float4*)&h_s[ty * HIDDEN + j0 + tx * 4];
        float4 dx;
        dx.x = tanhf(acc.x);
        dx.y = tanhf(acc.y);
        dx.z = tanhf(acc.z);
        dx.w = tanhf(acc.w);
        float4 hn;
        hn.x = hold.x + (dx.x - hold.x) * itau_s[tx * 4 + 0];
        hn.y = hold.y + (dx.y - hold.y) * itau_s[tx * 4 + 1];
        hn.z = hold.z + (dx.z - hold.z) * itau_s[tx * 4 + 2];
        hn.w = hold.w + (dx.w - hold.w) * itau_s[tx * 4 + 3];
        *(float4*)(g_h[cur ^ 1] + (size_t)(b0 + ty) * HIDDEN + j0 + tx * 4) = hn;

        grid_sync(sh_gen0 + (++nbar));
        cur ^= 1;
    }
    // cur == 0 after 512 flips; h_final = g_h[0]

    // ---------------- Phase 3: out = h_final @ W_out + b_out -----------------
    if (blockIdx.x < 64) {
        const int bt3 = blockIdx.x >> 3;   // 0..7
        const int ot  = blockIdx.x & 7;    // 0..7
        const int b03 = bt3 * 16;
        const int o0  = ot * 32;

        for (int q = tid; q < 16 * 256; q += 256) {
            int r = q >> 8, cq = q & 255;
            float4 v = __ldcg((const float4*)(g_h[cur] + (size_t)(b03 + r) * HIDDEN) + cq);
            *(float4*)&h_s[r * HIDDEN + cq * 4] = v;
        }
        __syncthreads();

        float a0 = bout[o0 + tx];
        float a1 = bout[o0 + tx + 16];
        float* wo_s = ws;   // reuse: [64][32] = 2048 floats

        for (int kc = 0; kc < HIDDEN; kc += 64) {
            __syncthreads();
#pragma unroll
            for (int u = 0; u < 2; ++u) {
                int idx = tid * 2 + u;       // 0..511 float4s
                int r = idx >> 3, c4 = idx & 7;
                *(float4*)&wo_s[r * 32 + c4 * 4] =
                    *(const float4*)(Wout + (size_t)(kc + r) * OUTPUT + o0 + c4 * 4);
            }
            __syncthreads();
#pragma unroll 16
            for (int kk = 0; kk < 64; ++kk) {
                float hv = h_s[ty * HIDDEN + kc + kk];
                a0 += hv * wo_s[kk * 32 + tx];
                a1 += hv * wo_s[kk * 32 + tx + 16];
            }
        }
        out[(size_t)(b03 + ty) * OUTPUT + o0 + tx]      = a0;
        out[(size_t)(b03 + ty) * OUTPUT + o0 + tx + 16] = a1;
    }
}

// ---------------------------------------------------------------------------
// Launch
// Inputs (metadata order): x, W_in, b_in, W_h, b_h, tau, W_out, b_out
// ---------------------------------------------------------------------------
extern "C" void kernel_launch(void* const* d_in, const int* in_sizes, int n_in,
                              void* d_out, int out_size)
{
    const float* x    = (const float*)d_in[0];
    const float* Win  = (const float*)d_in[1];
    const float* bin  = (const float*)d_in[2];
    const float* Wh   = (const float*)d_in[3];
    const float* bhp  = (const float*)d_in[4];
    const float* tau  = (const float*)d_in[5];
    const float* Wout = (const float*)d_in[6];
    const float* bout = (const float*)d_in[7];
    float* out = (float*)d_out;

    cudaFuncSetAttribute(scan_kernel, cudaFuncAttributeMaxDynamicSharedMemorySize,
                         SCAN_SMEM_BYTES);

    dim3 grid1(HIDDEN / 64, (BATCH * SEQ) / 64);   // 16 x 1024
    gemm_xin_kernel<<<grid1, 256>>>(x, Win, bin);

    scan_kernel<<<NBLK, 256, SCAN_SMEM_BYTES>>>(Wh, bhp, tau, Wout, bout, out);
}

// round 5
// speedup vs baseline: 1.6325x; 1.6325x over previous
#include <cuda_runtime.h>
#include <cuda_bf16.h>
#include <math.h>
#include <stdint.h>

#define BATCH   128
#define SEQ     512
#define INPUT   512
#define HIDDEN  1024
#define OUTPUT  256
#define NSCAN   32
#define JW      32

// ---------------- device scratch (no allocs allowed) ----------------
__device__ float          g_xin[(size_t)SEQ * BATCH * HIDDEN];  // [s][b][h]
__device__ float          g_hf[2][BATCH * HIDDEN];              // fp32 h ping-pong
__device__ __nv_bfloat16  g_hhi[2][BATCH * HIDDEN];             // h hi plane
__device__ __nv_bfloat16  g_hlo[2][BATCH * HIDDEN];             // h lo plane
__device__ unsigned g_bar_cnt;
__device__ unsigned g_bar_gen;

// ---------------- smem layout (bytes) ----------------
// W planes: [kblk(16)][n(32) rows][128 B], per-row XOR swizzle
#define OFF_WHI    0            // 64 KB
#define OFF_WLO    65536        // 64 KB
#define OFF_STAGE  131072       // 3 bufs x (hi 16KB + lo 16KB) = 96 KB
#define OFF_BH     229376       // 32 floats
#define OFF_ITAU   229504       // 32 floats
#define OFF_GEN0   229632
#define SCAN_SMEM  229760

__device__ __forceinline__ uint32_t smem_u32(const void* p) {
    uint32_t a;
    asm("{ .reg .u64 t; cvta.to.shared.u64 t, %1; cvt.u32.u64 %0, t; }" : "=r"(a) : "l"(p));
    return a;
}
#define CP_COMMIT() asm volatile("cp.async.commit_group;" ::: "memory")
#define CP_WAIT1()  asm volatile("cp.async.wait_group 1;" ::: "memory")
#define CP_WAIT0()  asm volatile("cp.async.wait_group 0;" ::: "memory")

__device__ __forceinline__ void cp16(uint32_t dst, const void* src) {
    asm volatile("cp.async.cg.shared.global [%0], [%1], 16;" :: "r"(dst), "l"(src) : "memory");
}
__device__ __forceinline__ void ldsm4(uint32_t& r0, uint32_t& r1, uint32_t& r2, uint32_t& r3,
                                      uint32_t a) {
    asm volatile("ldmatrix.sync.aligned.m8n8.x4.shared.b16 {%0,%1,%2,%3}, [%4];"
                 : "=r"(r0), "=r"(r1), "=r"(r2), "=r"(r3) : "r"(a));
}
__device__ __forceinline__ void mma16816(float* d, const uint32_t* a, uint32_t b0, uint32_t b1) {
    asm volatile("mma.sync.aligned.m16n8k16.row.col.f32.bf16.bf16.f32 "
                 "{%0,%1,%2,%3}, {%4,%5,%6,%7}, {%8,%9}, {%0,%1,%2,%3};"
                 : "+f"(d[0]), "+f"(d[1]), "+f"(d[2]), "+f"(d[3])
                 : "r"(a[0]), "r"(a[1]), "r"(a[2]), "r"(a[3]), "r"(b0), "r"(b1));
}

__device__ __forceinline__ void grid_sync(unsigned target)
{
    __threadfence();
    __syncthreads();
    if (threadIdx.x == 0) {
        unsigned arrived = atomicAdd(&g_bar_cnt, 1u);
        if (arrived == NSCAN - 1) {
            atomicExch(&g_bar_cnt, 0u);
            __threadfence();
            atomicAdd(&g_bar_gen, 1u);
        } else {
            while (*(volatile unsigned*)&g_bar_gen != target) { }
            __threadfence();
        }
    }
    __syncthreads();
}

__device__ __forceinline__ uint32_t pbf2(float a, float b) {
    __nv_bfloat162 t = __floats2bfloat162_rn(a, b);
    return *(uint32_t*)&t;
}

// ---------------------------------------------------------------------------
// Phase 1: xin = x @ W_in + b_in (SIMT fp32)
// ---------------------------------------------------------------------------
__global__ __launch_bounds__(256) void gemm_xin_kernel(
    const float* __restrict__ x, const float* __restrict__ Win, const float* __restrict__ bin)
{
    __shared__ float As[16][64];
    __shared__ float Bs[16][64];
    const int tid = threadIdx.x;
    const int m0 = blockIdx.y * 64, n0 = blockIdx.x * 64;
    const int ty = tid >> 4, tx = tid & 15;
    float acc[4][4];
#pragma unroll
    for (int i = 0; i < 4; ++i)
#pragma unroll
        for (int j = 0; j < 4; ++j) acc[i][j] = 0.0f;
    const int arow = tid >> 2, akq = tid & 3, brow = tid >> 4, bnq = tid & 15;
    for (int k0 = 0; k0 < INPUT; k0 += 16) {
        float4 av = *(const float4*)(x   + (size_t)(m0 + arow) * INPUT  + k0 + akq * 4);
        float4 bv = *(const float4*)(Win + (size_t)(k0 + brow) * HIDDEN + n0 + bnq * 4);
        __syncthreads();
        As[akq*4+0][arow] = av.x; As[akq*4+1][arow] = av.y;
        As[akq*4+2][arow] = av.z; As[akq*4+3][arow] = av.w;
        *(float4*)&Bs[brow][bnq*4] = bv;
        __syncthreads();
#pragma unroll
        for (int kk = 0; kk < 16; ++kk) {
            float4 a4 = *(const float4*)&As[kk][ty*4];
            float4 b4 = *(const float4*)&Bs[kk][tx*4];
            float a[4] = {a4.x, a4.y, a4.z, a4.w};
            float b[4] = {b4.x, b4.y, b4.z, b4.w};
#pragma unroll
            for (int i = 0; i < 4; ++i)
#pragma unroll
                for (int j = 0; j < 4; ++j) acc[i][j] += a[i] * b[j];
        }
    }
    float4 bi = *(const float4*)(bin + n0 + tx*4);
#pragma unroll
    for (int i = 0; i < 4; ++i) {
        int m = m0 + ty*4 + i;
        int b = m >> 9, s = m & 511;
        float4 r;
        r.x = acc[i][0]+bi.x; r.y = acc[i][1]+bi.y; r.z = acc[i][2]+bi.z; r.w = acc[i][3]+bi.w;
        *(float4*)(g_xin + ((size_t)s * BATCH + b) * HIDDEN + n0 + tx*4) = r;
    }
}

// ---------------------------------------------------------------------------
// stage one k64 chunk of h (hi+lo bf16) into a swizzled stage buffer
// rows m=0..127, 128 B per row (64 k)
// ---------------------------------------------------------------------------
__device__ __forceinline__ void stage_chunk(uint32_t sb, const __nv_bfloat16* hi_src,
                                            const __nv_bfloat16* lo_src, int cc, int tid)
{
    uint32_t base = sb + OFF_STAGE + (uint32_t)(cc % 3) * 32768u;
    const char* shi = (const char*)hi_src + (size_t)cc * 128;
    const char* slo = (const char*)lo_src + (size_t)cc * 128;
#pragma unroll
    for (int u = 0; u < 4; ++u) {
        int g = tid + u * 256;           // row(128) x seg(8)
        int r = g >> 3, s = g & 7;
        uint32_t d = (uint32_t)(r * 128) + (uint32_t)((s * 16) ^ ((r & 7) << 4));
        size_t off = (size_t)r * 2048 + (size_t)s * 16;
        cp16(base + d,         shi + off);
        cp16(base + 16384 + d, slo + off);
    }
}

// ---------------------------------------------------------------------------
// Phase 2+3: persistent mma.sync scan, 32 blocks x 256 threads
// block j-slice = 32 cols; warp w = m-tile rows [16w, 16w+16)
// ---------------------------------------------------------------------------
__global__ __launch_bounds__(256, 1) void scan_mma_kernel(
    const float* __restrict__ Wh,  const float* __restrict__ bh,
    const float* __restrict__ tau, const float* __restrict__ Wout,
    const float* __restrict__ bout, float* __restrict__ out)
{
    extern __shared__ __align__(1024) char smem[];
    const uint32_t sb = smem_u32(smem);
    const int tid = threadIdx.x, wid = tid >> 5, lid = tid & 31;
    const int j0 = blockIdx.x * JW;
    float* bh_s   = (float*)(smem + OFF_BH);
    float* itau_s = (float*)(smem + OFF_ITAU);

    if (tid == 0) *(unsigned*)(smem + OFF_GEN0) = *(volatile unsigned*)&g_bar_gen;
    if (tid < JW) {
        bh_s[tid]   = bh[j0 + tid];
        itau_s[tid] = 1.0f / tau[j0 + tid];
    }

    // ---- prologue: W slice -> SMEM bf16 hi/lo, [kblk][n][128B] swizzled
    for (int idx = tid; idx < 1024 * 8; idx += 256) {     // k(1024) x nq(8)
        int k = idx >> 3, nq = idx & 7;
        float4 wv = *(const float4*)(Wh + (size_t)k * HIDDEN + j0 + nq * 4);
        float w[4] = {wv.x, wv.y, wv.z, wv.w};
#pragma unroll
        for (int e = 0; e < 4; ++e) {
            int n = nq * 4 + e;
            uint32_t so = (uint32_t)((k >> 6) * 4096 + n * 128)
                        + (uint32_t)((((k & 63) * 2) ^ ((n & 7) << 4)));
            __nv_bfloat16 whi = __float2bfloat16(w[e]);
            __nv_bfloat16 wlo = __float2bfloat16(w[e] - __bfloat162float(whi));
            *(__nv_bfloat16*)(smem + OFF_WHI + so) = whi;
            *(__nv_bfloat16*)(smem + OFF_WLO + so) = wlo;
        }
    }

    // ---- zero h0: own j-slice (fp32 + planes)
    for (int idx = tid; idx < BATCH * JW / 2; idx += 256) {
        int r = idx / (JW / 2), c = idx % (JW / 2);
        *(float2*)(g_hf[0]    + (size_t)r * HIDDEN + j0 + c * 2) = make_float2(0.f, 0.f);
        *(uint32_t*)(g_hhi[0] + (size_t)r * HIDDEN + j0 + c * 2) = 0u;
        *(uint32_t*)(g_hlo[0] + (size_t)r * HIDDEN + j0 + c * 2) = 0u;
    }
    __syncthreads();
    const unsigned gen0 = *(unsigned*)(smem + OFF_GEN0);

    unsigned nbar = 0;
    grid_sync(gen0 + (++nbar));

    // per-lane ldmatrix geometry
    const int m0  = wid * 16;
    const int grp = lid >> 3;
    // A: M0 rows m0..7 @k0 | M1 m8..15 @k0 | M2 m0..7 @k8 | M3 m8..15 @k8
    const int a_row  = m0 + (lid & 7) + ((grp & 1) << 3);
    const int a_koff = (grp >> 1) << 4;                  // 0 or 16 bytes
    const uint32_t a_rowbase = (uint32_t)(a_row * 128);
    const uint32_t a_xor     = (uint32_t)((a_row & 7) << 4);
    // B: x4 load covers 2 n-tiles: {n0-7,k0} {n0-7,k8} {n8-15,k0} {n8-15,k8}
    const int b_nrow = (lid & 7) + ((grp >> 1) << 3);    // 0..15 (+16 for second load)
    const int b_koff = (grp & 1) << 4;
    const uint32_t b_xor0 = (uint32_t)((b_nrow & 7) << 4);

    // epilogue geometry
    const int er = lid >> 2, ec = (lid & 3) * 2;

    int cur = 0;
    for (int t = 0; t < SEQ; ++t) {
        const __nv_bfloat16* hhi = g_hhi[cur];
        const __nv_bfloat16* hlo = g_hlo[cur];

        // prefetch xin + h_old in fragment layout: [rt(2)][ntile(4)]
        float2 xv[8], hv[8];
#pragma unroll
        for (int rt = 0; rt < 2; ++rt) {
            int row = m0 + er + rt * 8;
            const float* xp = g_xin + ((size_t)t * BATCH + row) * HIDDEN + j0;
            const float* hp = g_hf[cur] + (size_t)row * HIDDEN + j0;
#pragma unroll
            for (int j = 0; j < 4; ++j) {
                xv[rt * 4 + j] = *(const float2*)(xp + j * 8 + ec);
                hv[rt * 4 + j] = *(const float2*)(hp + j * 8 + ec);
            }
        }

        float acc[4][4];
#pragma unroll
        for (int j = 0; j < 4; ++j)
#pragma unroll
            for (int r = 0; r < 4; ++r) acc[j][r] = 0.0f;

        stage_chunk(sb, hhi, hlo, 0, tid); CP_COMMIT();
        stage_chunk(sb, hhi, hlo, 1, tid); CP_COMMIT();

        for (int c = 0; c < 16; ++c) {
            CP_WAIT1();
            __syncthreads();
            if (c + 2 < 16) { stage_chunk(sb, hhi, hlo, c + 2, tid); }
            CP_COMMIT();

            const uint32_t abuf = sb + OFF_STAGE + (uint32_t)(c % 3) * 32768u;
            const uint32_t wbase_hi = sb + OFF_WHI + (uint32_t)(c * 4096);
#pragma unroll
            for (int k2 = 0; k2 < 4; ++k2) {
                const uint32_t kb = (uint32_t)(k2 * 32);
                uint32_t ahi[4], alo[4];
                {
                    uint32_t aa = abuf + a_rowbase + ((kb + a_koff) ^ a_xor);
                    ldsm4(ahi[0], ahi[1], ahi[2], ahi[3], aa);
                    ldsm4(alo[0], alo[1], alo[2], alo[3], aa + 16384);
                }
                uint32_t bhi[8], blo[8];
                {
                    uint32_t b0a = wbase_hi + (uint32_t)(b_nrow * 128) + ((kb + b_koff) ^ b_xor0);
                    ldsm4(bhi[0], bhi[1], bhi[2], bhi[3], b0a);
                    uint32_t b1a = b0a + 16u * 128u;          // n rows +16, same (n&7)
                    ldsm4(bhi[4], bhi[5], bhi[6], bhi[7], b1a);
                    ldsm4(blo[0], blo[1], blo[2], blo[3], b0a + (OFF_WLO - OFF_WHI));
                    ldsm4(blo[4], blo[5], blo[6], blo[7], b1a + (OFF_WLO - OFF_WHI));
                }
#pragma unroll
                for (int j = 0; j < 4; ++j) {
                    mma16816(acc[j], ahi, bhi[j * 2], bhi[j * 2 + 1]);   // hi*hi
                    mma16816(acc[j], alo, bhi[j * 2], bhi[j * 2 + 1]);   // lo*hi
                    mma16816(acc[j], ahi, blo[j * 2], blo[j * 2 + 1]);   // hi*lo
                }
            }
        }
        CP_WAIT0();

        // ---- epilogue: z = D + xin + bh ; dx = tanh ; h' = h + (dx-h)/tau
        {
            float*    hfn = g_hf[cur ^ 1];
            uint32_t* hhn = (uint32_t*)g_hhi[cur ^ 1];
            uint32_t* hln = (uint32_t*)g_hlo[cur ^ 1];
#pragma unroll
            for (int rt = 0; rt < 2; ++rt) {
                int row = m0 + er + rt * 8;
                size_t rb = (size_t)row * HIDDEN + j0;
#pragma unroll
                for (int j = 0; j < 4; ++j) {
                    int n = j * 8 + ec;
                    float2 xx = xv[rt * 4 + j], hh = hv[rt * 4 + j];
                    float z0 = acc[j][rt * 2 + 0] + xx.x + bh_s[n];
                    float z1 = acc[j][rt * 2 + 1] + xx.y + bh_s[n + 1];
                    float d0 = tanhf(z0), d1 = tanhf(z1);
                    float h0 = hh.x + (d0 - hh.x) * itau_s[n];
                    float h1 = hh.y + (d1 - hh.y) * itau_s[n + 1];
                    *(float2*)(hfn + rb + n) = make_float2(h0, h1);
                    __nv_bfloat16 b0 = __float2bfloat16(h0);
                    __nv_bfloat16 b1 = __float2bfloat16(h1);
                    float l0 = h0 - __bfloat162float(b0);
                    float l1 = h1 - __bfloat162float(b1);
                    hhn[(rb + n) >> 1] = pbf2(h0, h1);
                    hln[(rb + n) >> 1] = pbf2(l0, l1);
                }
            }
        }
        grid_sync(gen0 + (++nbar));
        cur ^= 1;
    }
    // cur == 0; final h in g_hf[0]

    // ---- Phase 3: out = h_final @ W_out + b_out ----
    {
        const int b03 = (blockIdx.x >> 3) * 32;
        const int o0  = (blockIdx.x & 7) * 32;
        float* h_s  = (float*)smem;                  // [32][1024] reuse W region
        float* wo_s = (float*)(smem + OFF_STAGE);    // [64][32]
        for (int q = tid; q < 32 * 256; q += 256) {
            int r = q >> 8, cq = q & 255;
            float4 v = __ldcg((const float4*)(g_hf[cur] + (size_t)(b03 + r) * HIDDEN) + cq);
            *(float4*)&h_s[r * HIDDEN + cq * 4] = v;
        }
        const int ty = tid >> 3, tx = tid & 7;
        float4 acc = *(const float4*)(bout + o0 + tx * 4);
        for (int kc = 0; kc < 16; ++kc) {
            __syncthreads();
#pragma unroll
            for (int u = 0; u < 2; ++u) {
                int idx = tid * 2 + u;
                int r = idx >> 3, c4 = idx & 7;
                *(float4*)&wo_s[r * 32 + c4 * 4] =
                    *(const float4*)(Wout + (size_t)(kc * 64 + r) * OUTPUT + o0 + c4 * 4);
            }
            __syncthreads();
#pragma unroll 16
            for (int kk = 0; kk < 64; ++kk) {
                float hvv = h_s[ty * HIDDEN + kc * 64 + kk];
                float4 w = *(const float4*)&wo_s[kk * 32 + tx * 4];
                acc.x += hvv * w.x; acc.y += hvv * w.y;
                acc.z += hvv * w.z; acc.w += hvv * w.w;
            }
        }
        *(float4*)(out + (size_t)(b03 + ty) * OUTPUT + o0 + tx * 4) = acc;
    }
}

// ---------------------------------------------------------------------------
// Launch. Inputs: x, W_in, b_in, W_h, b_h, tau, W_out, b_out
// ---------------------------------------------------------------------------
extern "C" void kernel_launch(void* const* d_in, const int* in_sizes, int n_in,
                              void* d_out, int out_size)
{
    const float* x    = (const float*)d_in[0];
    const float* Win  = (const float*)d_in[1];
    const float* bin  = (const float*)d_in[2];
    const float* Wh   = (const float*)d_in[3];
    const float* bhp  = (const float*)d_in[4];
    const float* tau  = (const float*)d_in[5];
    const float* Wout = (const float*)d_in[6];
    const float* bout = (const float*)d_in[7];
    float* out = (float*)d_out;

    cudaFuncSetAttribute(scan_mma_kernel, cudaFuncAttributeMaxDynamicSharedMemorySize, SCAN_SMEM);

    dim3 grid1(HIDDEN / 64, (BATCH * SEQ) / 64);
    gemm_xin_kernel<<<grid1, 256>>>(x, Win, bin);

    scan_mma_kernel<<<NSCAN, 256, SCAN_SMEM>>>(Wh, bhp, tau, Wout, bout, out);
}

// round 6
// speedup vs baseline: 4.1879x; 2.5653x over previous
#include <cuda_runtime.h>
#include <cuda_bf16.h>
#include <math.h>
#include <stdint.h>

#define BATCH   128
#define SEQ     512
#define INPUT   512
#define HIDDEN  1024
#define OUTPUT  256
#define NBLK    128
#define JW      32
#define MW      32

// ---------------- device scratch (no allocs allowed) ----------------
__device__ float          g_xin[(size_t)SEQ * BATCH * HIDDEN];   // [s][b][h]
__device__ float          g_hf[2][BATCH * HIDDEN];
__device__ __nv_bfloat16  g_hhi[2][BATCH * HIDDEN];
__device__ __nv_bfloat16  g_hlo[2][BATCH * HIDDEN];
__device__ __nv_bfloat16  g_xhi[(size_t)BATCH * SEQ * INPUT];    // x planes [m][k]
__device__ __nv_bfloat16  g_xlo[(size_t)BATCH * SEQ * INPUT];
__device__ __nv_bfloat16  g_wThi[HIDDEN * INPUT];                // W_in^T planes [n][k]
__device__ __nv_bfloat16  g_wTlo[HIDDEN * INPUT];
__device__ unsigned g_bar_cnt;
__device__ unsigned g_bar_gen;

// ---------------- scan smem layout ----------------
#define OFF_WHI    0                 // [kblk16][n32][128B] 64 KB
#define OFF_WLO    65536             // 64 KB
#define OFF_STAGE  131072            // 3 slots x 16 KB (pair: hi[2][32][128B], lo[...])
#define OFF_RED    180224            // 4 KB k-reduction
#define OFF_BH     184320
#define OFF_ITAU   184448
#define OFF_GEN0   184576
#define SCAN_SMEM  184640

// ---------------- gemm smem layout ----------------
#define OFF_GA     0                 // 3 bufs x (hi 16KB + lo 16KB)
#define OFF_GB     98304             // 3 bufs x (hi 8KB + lo 8KB)
#define OFF_BIN    147456
#define GEMM_SMEM  147968

__device__ __forceinline__ uint32_t smem_u32(const void* p) {
    uint32_t a;
    asm("{ .reg .u64 t; cvta.to.shared.u64 t, %1; cvt.u32.u64 %0, t; }" : "=r"(a) : "l"(p));
    return a;
}
#define CP_COMMIT() asm volatile("cp.async.commit_group;" ::: "memory")
#define CP_WAIT1()  asm volatile("cp.async.wait_group 1;" ::: "memory")

__device__ __forceinline__ void cp16(uint32_t dst, const void* src) {
    asm volatile("cp.async.cg.shared.global [%0], [%1], 16;" :: "r"(dst), "l"(src) : "memory");
}
__device__ __forceinline__ void ldsm4(uint32_t& r0, uint32_t& r1, uint32_t& r2, uint32_t& r3,
                                      uint32_t a) {
    asm volatile("ldmatrix.sync.aligned.m8n8.x4.shared.b16 {%0,%1,%2,%3}, [%4];"
                 : "=r"(r0), "=r"(r1), "=r"(r2), "=r"(r3) : "r"(a));
}
__device__ __forceinline__ void mma16816(float* d, const uint32_t* a, uint32_t b0, uint32_t b1) {
    asm volatile("mma.sync.aligned.m16n8k16.row.col.f32.bf16.bf16.f32 "
                 "{%0,%1,%2,%3}, {%4,%5,%6,%7}, {%8,%9}, {%0,%1,%2,%3};"
                 : "+f"(d[0]), "+f"(d[1]), "+f"(d[2]), "+f"(d[3])
                 : "r"(a[0]), "r"(a[1]), "r"(a[2]), "r"(a[3]), "r"(b0), "r"(b1));
}

__device__ __forceinline__ void grid_sync(unsigned target)
{
    __threadfence();
    __syncthreads();
    if (threadIdx.x == 0) {
        unsigned arrived = atomicAdd(&g_bar_cnt, 1u);
        if (arrived == NBLK - 1) {
            atomicExch(&g_bar_cnt, 0u);
            __threadfence();
            atomicAdd(&g_bar_gen, 1u);
        } else {
            while (*(volatile unsigned*)&g_bar_gen != target) { }
            __threadfence();
        }
    }
    __syncthreads();
}

__device__ __forceinline__ uint32_t pbf2(float a, float b) {
    __nv_bfloat162 t = __floats2bfloat162_rn(a, b);
    return *(uint32_t*)&t;
}

// ---------------------------------------------------------------------------
// Conversion kernels: fp32 -> bf16 hi/lo planes
// ---------------------------------------------------------------------------
__global__ __launch_bounds__(256) void conv_x_kernel(const float* __restrict__ x)
{
    const size_t total = (size_t)BATCH * SEQ * INPUT / 2;   // float2 count
    size_t base = (size_t)blockIdx.x * 256 + threadIdx.x;
    size_t stride = (size_t)gridDim.x * 256;
    uint32_t* xhi = (uint32_t*)g_xhi;
    uint32_t* xlo = (uint32_t*)g_xlo;
    for (size_t p = base; p < total; p += stride) {
        float2 v = ((const float2*)x)[p];
        __nv_bfloat16 h0 = __float2bfloat16(v.x);
        __nv_bfloat16 h1 = __float2bfloat16(v.y);
        float l0 = v.x - __bfloat162float(h0);
        float l1 = v.y - __bfloat162float(h1);
        xhi[p] = pbf2(v.x, v.y);          // rn-packed hi
        // recompute lo against rn-rounded hi for exact split
        __nv_bfloat162 hp = *(__nv_bfloat162*)&xhi[p];
        l0 = v.x - __bfloat162float(hp.x);
        l1 = v.y - __bfloat162float(hp.y);
        xlo[p] = pbf2(l0, l1);
        (void)h0; (void)h1;
    }
}

__global__ __launch_bounds__(256) void conv_w_kernel(const float* __restrict__ Win)
{
    int idx = blockIdx.x * 256 + threadIdx.x;     // 0 .. 512K-1
    if (idx >= INPUT * HIDDEN) return;
    int k = idx >> 10, n = idx & 1023;
    float w = Win[idx];
    __nv_bfloat16 whi = __float2bfloat16(w);
    float lo = w - __bfloat162float(whi);
    g_wThi[(size_t)n * INPUT + k] = whi;
    g_wTlo[(size_t)n * INPUT + k] = __float2bfloat16(lo);
}

// ---------------------------------------------------------------------------
// Phase 1: xin = x @ W_in + b_in  (bf16x3 mma). Block: M=128, N=64, K=512.
// ---------------------------------------------------------------------------
__device__ __forceinline__ void gstage(uint32_t sb, int kc, int m0, int n0, int tid)
{
    uint32_t abase = sb + OFF_GA + (uint32_t)(kc % 3) * 32768u;
    uint32_t bbase = sb + OFF_GB + (uint32_t)(kc % 3) * 16384u;
#pragma unroll
    for (int u = 0; u < 8; ++u) {                  // A: 2048 cp16
        int g = tid + u * 256;
        int seg = g & 7, row = (g >> 3) & 127, plane = g >> 10;
        const char* src = (const char*)(plane ? g_xlo : g_xhi)
                        + (size_t)(m0 + row) * 1024 + (size_t)kc * 128 + seg * 16;
        uint32_t dst = abase + plane * 16384 + row * 128 + ((seg * 16) ^ ((row & 7) << 4));
        cp16(dst, src);
    }
#pragma unroll
    for (int u = 0; u < 4; ++u) {                  // B: 1024 cp16
        int g = tid + u * 256;
        int seg = g & 7, row = (g >> 3) & 63, plane = g >> 9;
        const char* src = (const char*)(plane ? g_wTlo : g_wThi)
                        + (size_t)(n0 + row) * 1024 + (size_t)kc * 128 + seg * 16;
        uint32_t dst = bbase + plane * 8192 + row * 128 + ((seg * 16) ^ ((row & 7) << 4));
        cp16(dst, src);
    }
}

__global__ __launch_bounds__(256, 1) void gemm_xin_mma(const float* __restrict__ bin)
{
    extern __shared__ __align__(1024) char smem[];
    const uint32_t sb = smem_u32(smem);
    const int tid = threadIdx.x, wid = tid >> 5, lid = tid & 31;
    const int n0 = blockIdx.x * 64, m0 = blockIdx.y * 128;
    const int mq = wid & 3, nh = wid >> 2;
    float* bin_s = (float*)(smem + OFF_BIN);
    if (tid < 16) ((float4*)bin_s)[tid] = ((const float4*)(bin + n0))[tid];

    const int grp = lid >> 3;
    int a_rowl[2];
    a_rowl[0] = mq * 32 + (lid & 7) + ((grp & 1) << 3);
    a_rowl[1] = a_rowl[0] + 16;
    const int a_koff = (grp >> 1) << 4;
    const int b_nr   = nh * 32 + (lid & 7) + ((grp >> 1) << 3);
    const int b_koff = (grp & 1) << 4;
    const uint32_t b_xor = (uint32_t)((b_nr & 7) << 4);

    float acc[2][4][4];
#pragma unroll
    for (int i = 0; i < 2; ++i)
#pragma unroll
        for (int j = 0; j < 4; ++j)
#pragma unroll
            for (int r = 0; r < 4; ++r) acc[i][j][r] = 0.0f;

    gstage(sb, 0, m0, n0, tid); CP_COMMIT();
    gstage(sb, 1, m0, n0, tid); CP_COMMIT();

    for (int kc = 0; kc < 8; ++kc) {
        CP_WAIT1();
        __syncthreads();
        if (kc + 2 < 8) gstage(sb, kc + 2, m0, n0, tid);
        CP_COMMIT();
        const uint32_t abase = sb + OFF_GA + (uint32_t)(kc % 3) * 32768u;
        const uint32_t bbase = sb + OFF_GB + (uint32_t)(kc % 3) * 16384u;
#pragma unroll
        for (int k2 = 0; k2 < 4; ++k2) {
            const uint32_t kb = (uint32_t)(k2 * 32);
            uint32_t ahi[2][4], alo[2][4];
#pragma unroll
            for (int mt = 0; mt < 2; ++mt) {
                uint32_t aa = abase + (uint32_t)(a_rowl[mt] * 128)
                            + ((kb + a_koff) ^ ((a_rowl[mt] & 7) << 4));
                ldsm4(ahi[mt][0], ahi[mt][1], ahi[mt][2], ahi[mt][3], aa);
                ldsm4(alo[mt][0], alo[mt][1], alo[mt][2], alo[mt][3], aa + 16384);
            }
            uint32_t bhi[8], blo[8];
            {
                uint32_t ba = bbase + (uint32_t)(b_nr * 128) + ((kb + b_koff) ^ b_xor);
                ldsm4(bhi[0], bhi[1], bhi[2], bhi[3], ba);
                ldsm4(bhi[4], bhi[5], bhi[6], bhi[7], ba + 2048);      // n rows +16
                ldsm4(blo[0], blo[1], blo[2], blo[3], ba + 8192);
                ldsm4(blo[4], blo[5], blo[6], blo[7], ba + 8192 + 2048);
            }
#pragma unroll
            for (int mt = 0; mt < 2; ++mt)
#pragma unroll
                for (int j = 0; j < 4; ++j) {
                    mma16816(acc[mt][j], ahi[mt], bhi[j * 2], bhi[j * 2 + 1]);
                    mma16816(acc[mt][j], alo[mt], bhi[j * 2], bhi[j * 2 + 1]);
                    mma16816(acc[mt][j], ahi[mt], blo[j * 2], blo[j * 2 + 1]);
                }
        }
    }

    const int er = lid >> 2, ec = (lid & 3) * 2;
#pragma unroll
    for (int mt = 0; mt < 2; ++mt)
#pragma unroll
        for (int rt = 0; rt < 2; ++rt) {
            int m = m0 + mq * 32 + mt * 16 + er + rt * 8;
            int b = m >> 9, s = m & 511;
            float* orow = g_xin + ((size_t)s * BATCH + b) * HIDDEN + n0;
#pragma unroll
            for (int j = 0; j < 4; ++j) {
                int nl = nh * 32 + j * 8 + ec;
                float2 v;
                v.x = acc[mt][j][rt * 2 + 0] + bin_s[nl];
                v.y = acc[mt][j][rt * 2 + 1] + bin_s[nl + 1];
                *(float2*)(orow + nl) = v;
            }
        }
}

// ---------------------------------------------------------------------------
// Scan: 128 blocks = 32 j-tiles x 4 m-tiles(32 rows). 8 warps = 2m x 2n x 2k.
// ---------------------------------------------------------------------------
__device__ __forceinline__ void stage_pair(uint32_t sb, const __nv_bfloat16* hi,
                                           const __nv_bfloat16* lo, int i, int m0, int tid)
{
    uint32_t base = sb + OFF_STAGE + (uint32_t)(i % 3) * 16384u;
#pragma unroll
    for (int u = 0; u < 4; ++u) {
        int g = tid + u * 256;                   // plane(2) x half(2) x row(32) x seg(8)
        int seg = g & 7, row = (g >> 3) & 31, half = (g >> 8) & 1, plane = g >> 9;
        const char* src = (const char*)(plane ? lo : hi)
                        + (size_t)(m0 + row) * 2048 + (size_t)(i + half * 8) * 128 + seg * 16;
        uint32_t dst = base + plane * 8192 + half * 4096 + row * 128
                     + ((seg * 16) ^ ((row & 7) << 4));
        cp16(dst, src);
    }
}

__global__ __launch_bounds__(256, 1) void scan_mma_kernel(
    const float* __restrict__ Wh,  const float* __restrict__ bh,
    const float* __restrict__ tau, const float* __restrict__ Wout,
    const float* __restrict__ bout, float* __restrict__ out)
{
    extern __shared__ __align__(1024) char smem[];
    const uint32_t sb = smem_u32(smem);
    const int tid = threadIdx.x, wid = tid >> 5, lid = tid & 31;
    const int jt = blockIdx.x >> 2, mt_blk = blockIdx.x & 3;
    const int j0 = jt * JW, m0 = mt_blk * MW;
    float* bh_s   = (float*)(smem + OFF_BH);
    float* itau_s = (float*)(smem + OFF_ITAU);
    float* red    = (float*)(smem + OFF_RED);

    if (tid == 0) *(unsigned*)(smem + OFF_GEN0) = *(volatile unsigned*)&g_bar_gen;
    if (tid < JW) {
        bh_s[tid]   = bh[j0 + tid];
        itau_s[tid] = 1.0f / tau[j0 + tid];
    }

    // W slice -> SMEM bf16 hi/lo, [kblk16][n32][128B] swizzled
    for (int idx = tid; idx < 1024 * 8; idx += 256) {
        int k = idx >> 3, nq = idx & 7;
        float4 wv = *(const float4*)(Wh + (size_t)k * HIDDEN + j0 + nq * 4);
        float w[4] = {wv.x, wv.y, wv.z, wv.w};
#pragma unroll
        for (int e = 0; e < 4; ++e) {
            int n = nq * 4 + e;
            uint32_t so = (uint32_t)((k >> 6) * 4096 + n * 128)
                        + (uint32_t)((((k & 63) * 2) ^ ((n & 7) << 4)));
            __nv_bfloat16 whi = __float2bfloat16(w[e]);
            __nv_bfloat16 wlo = __float2bfloat16(w[e] - __bfloat162float(whi));
            *(__nv_bfloat16*)(smem + OFF_WHI + so) = whi;
            *(__nv_bfloat16*)(smem + OFF_WLO + so) = wlo;
        }
    }

    // zero own h patch
    for (int idx = tid; idx < MW * JW / 2; idx += 256) {
        int r = idx / (JW / 2), c = idx % (JW / 2);
        size_t o = (size_t)(m0 + r) * HIDDEN + j0 + c * 2;
        *(float2*)(g_hf[0] + o) = make_float2(0.f, 0.f);
        *(uint32_t*)(g_hhi[0] + o) = 0u;
        *(uint32_t*)(g_hlo[0] + o) = 0u;
    }
    __syncthreads();
    const unsigned gen0 = *(unsigned*)(smem + OFF_GEN0);

    unsigned nbar = 0;
    grid_sync(gen0 + (++nbar));

    // warp roles
    const int w_mt = wid & 1, w_nh = (wid >> 1) & 1, w_kh = wid >> 2;
    const int grp = lid >> 3;
    const int a_row  = w_mt * 16 + (lid & 7) + ((grp & 1) << 3);   // 0..31 local
    const int a_koff = (grp >> 1) << 4;
    const uint32_t a_off = (uint32_t)(a_row * 128);
    const uint32_t a_xor = (uint32_t)((a_row & 7) << 4);
    const int b_nr   = w_nh * 16 + (lid & 7) + ((grp >> 1) << 3);  // 0..31 local
    const int b_koff = (grp & 1) << 4;
    const uint32_t b_xor = (uint32_t)((b_nr & 7) << 4);
    const int er = lid >> 2, ec = (lid & 3) * 2;
    const int rslot = (w_mt * 2 + w_nh) * 256;

    int cur = 0;
    for (int t = 0; t < SEQ; ++t) {
        const __nv_bfloat16* hhi = g_hhi[cur];
        const __nv_bfloat16* hlo = g_hlo[cur];

        float2 xv[2][2], hv[2][2];
        if (w_kh == 0) {
#pragma unroll
            for (int rt = 0; rt < 2; ++rt) {
                int row = m0 + w_mt * 16 + er + rt * 8;
                const float* xp = g_xin + ((size_t)t * BATCH + row) * HIDDEN + j0;
                const float* hp = g_hf[cur] + (size_t)row * HIDDEN + j0;
#pragma unroll
                for (int j = 0; j < 2; ++j) {
                    int nl = w_nh * 16 + j * 8 + ec;
                    xv[rt][j] = *(const float2*)(xp + nl);
                    hv[rt][j] = *(const float2*)(hp + nl);
                }
            }
        }

        float acc[2][4];
#pragma unroll
        for (int j = 0; j < 2; ++j)
#pragma unroll
            for (int r = 0; r < 4; ++r) acc[j][r] = 0.0f;

        stage_pair(sb, hhi, hlo, 0, m0, tid); CP_COMMIT();
        stage_pair(sb, hhi, hlo, 1, m0, tid); CP_COMMIT();

        for (int i = 0; i < 8; ++i) {
            CP_WAIT1();
            __syncthreads();
            if (i + 2 < 8) stage_pair(sb, hhi, hlo, i + 2, m0, tid);
            CP_COMMIT();

            const uint32_t base = sb + OFF_STAGE + (uint32_t)(i % 3) * 16384u
                                + (uint32_t)(w_kh * 4096);
            const int c = i + w_kh * 8;
            const uint32_t wbase = sb + OFF_WHI + (uint32_t)(c * 4096);
#pragma unroll
            for (int k2 = 0; k2 < 4; ++k2) {
                const uint32_t kb = (uint32_t)(k2 * 32);
                uint32_t ahi[4], alo[4];
                uint32_t aa = base + a_off + ((kb + a_koff) ^ a_xor);
                ldsm4(ahi[0], ahi[1], ahi[2], ahi[3], aa);
                ldsm4(alo[0], alo[1], alo[2], alo[3], aa + 8192);
                uint32_t bhi[4], blo[4];
                uint32_t ba = wbase + (uint32_t)(b_nr * 128) + ((kb + b_koff) ^ b_xor);
                ldsm4(bhi[0], bhi[1], bhi[2], bhi[3], ba);
                ldsm4(blo[0], blo[1], blo[2], blo[3], ba + (OFF_WLO - OFF_WHI));
#pragma unroll
                for (int j = 0; j < 2; ++j) {
                    mma16816(acc[j], ahi, bhi[j * 2], bhi[j * 2 + 1]);
                    mma16816(acc[j], alo, bhi[j * 2], bhi[j * 2 + 1]);
                    mma16816(acc[j], ahi, blo[j * 2], blo[j * 2 + 1]);
                }
            }
        }

        // k-reduction: kh=1 warps publish partials
        __syncthreads();
        if (w_kh == 1) {
#pragma unroll
            for (int rt = 0; rt < 2; ++rt)
#pragma unroll
                for (int j = 0; j < 2; ++j)
                    *(float2*)&red[rslot + (rt * 8 + er) * 16 + j * 8 + ec] =
                        make_float2(acc[j][rt * 2], acc[j][rt * 2 + 1]);
        }
        __syncthreads();

        if (w_kh == 0) {
            float*    hfn = g_hf[cur ^ 1];
            uint32_t* hhn = (uint32_t*)g_hhi[cur ^ 1];
            uint32_t* hln = (uint32_t*)g_hlo[cur ^ 1];
#pragma unroll
            for (int rt = 0; rt < 2; ++rt) {
                int row = m0 + w_mt * 16 + er + rt * 8;
                size_t rb = (size_t)row * HIDDEN + j0;
#pragma unroll
                for (int j = 0; j < 2; ++j) {
                    int nl = w_nh * 16 + j * 8 + ec;
                    float2 pp = *(float2*)&red[rslot + (rt * 8 + er) * 16 + j * 8 + ec];
                    float z0 = acc[j][rt * 2 + 0] + pp.x + xv[rt][j].x + bh_s[nl];
                    float z1 = acc[j][rt * 2 + 1] + pp.y + xv[rt][j].y + bh_s[nl + 1];
                    float d0 = tanhf(z0), d1 = tanhf(z1);
                    float h0 = hv[rt][j].x + (d0 - hv[rt][j].x) * itau_s[nl];
                    float h1 = hv[rt][j].y + (d1 - hv[rt][j].y) * itau_s[nl + 1];
                    *(float2*)(hfn + rb + nl) = make_float2(h0, h1);
                    __nv_bfloat16 b0 = __float2bfloat16(h0);
                    __nv_bfloat16 b1 = __float2bfloat16(h1);
                    hhn[(rb + nl) >> 1] = pbf2(h0, h1);
                    hln[(rb + nl) >> 1] = pbf2(h0 - __bfloat162float(b0),
                                               h1 - __bfloat162float(b1));
                }
            }
        }
        grid_sync(gen0 + (++nbar));
        cur ^= 1;
    }
    // cur == 0; final h in g_hf[0]

    // ---- Phase 3: out = h_final @ W_out + b_out (blocks 0..31) ----
    if (blockIdx.x < 32) {
        const int b03 = (blockIdx.x >> 3) * 32;
        const int o0  = (blockIdx.x & 7) * 32;
        float* h_s  = (float*)smem;                  // [32][1024]
        float* wo_s = (float*)(smem + OFF_STAGE);    // [64][32]
        for (int q = tid; q < 32 * 256; q += 256) {
            int r = q >> 8, cq = q & 255;
            float4 v = __ldcg((const float4*)(g_hf[cur] + (size_t)(b03 + r) * HIDDEN) + cq);
            *(float4*)&h_s[r * HIDDEN + cq * 4] = v;
        }
        const int ty = tid >> 3, tx = tid & 7;
        float4 acc = *(const float4*)(bout + o0 + tx * 4);
        for (int kc = 0; kc < 16; ++kc) {
            __syncthreads();
#pragma unroll
            for (int u = 0; u < 2; ++u) {
                int idx = tid * 2 + u;
                int r = idx >> 3, c4 = idx & 7;
                *(float4*)&wo_s[r * 32 + c4 * 4] =
                    *(const float4*)(Wout + (size_t)(kc * 64 + r) * OUTPUT + o0 + c4 * 4);
            }
            __syncthreads();
#pragma unroll 16
            for (int kk = 0; kk < 64; ++kk) {
                float hvv = h_s[ty * HIDDEN + kc * 64 + kk];
                float4 w = *(const float4*)&wo_s[kk * 32 + tx * 4];
                acc.x += hvv * w.x; acc.y += hvv * w.y;
                acc.z += hvv * w.z; acc.w += hvv * w.w;
            }
        }
        *(float4*)(out + (size_t)(b03 + ty) * OUTPUT + o0 + tx * 4) = acc;
    }
}

// ---------------------------------------------------------------------------
// Launch. Inputs: x, W_in, b_in, W_h, b_h, tau, W_out, b_out
// ---------------------------------------------------------------------------
extern "C" void kernel_launch(void* const* d_in, const int* in_sizes, int n_in,
                              void* d_out, int out_size)
{
    const float* x    = (const float*)d_in[0];
    const float* Win  = (const float*)d_in[1];
    const float* bin  = (const float*)d_in[2];
    const float* Wh   = (const float*)d_in[3];
    const float* bhp  = (const float*)d_in[4];
    const float* tau  = (const float*)d_in[5];
    const float* Wout = (const float*)d_in[6];
    const float* bout = (const float*)d_in[7];
    float* out = (float*)d_out;

    cudaFuncSetAttribute(gemm_xin_mma, cudaFuncAttributeMaxDynamicSharedMemorySize, GEMM_SMEM);
    cudaFuncSetAttribute(scan_mma_kernel, cudaFuncAttributeMaxDynamicSharedMemorySize, SCAN_SMEM);

    conv_x_kernel<<<4096, 256>>>(x);
    conv_w_kernel<<<(INPUT * HIDDEN + 255) / 256, 256>>>(Win);

    dim3 gg(HIDDEN / 64, (BATCH * SEQ) / 128);   // 16 x 512
    gemm_xin_mma<<<gg, 256, GEMM_SMEM>>>(bin);

    scan_mma_kernel<<<NBLK, 256, SCAN_SMEM>>>(Wh, bhp, tau, Wout, bout, out);
}